// round 3
// baseline (speedup 1.0000x reference)
#include <cuda_runtime.h>

// Problem constants
#define BDIM 8
#define NPTS 8192
#define SPTS 2048
#define D1C  64
#define D2C  256
#define C1C  256
#define C2C  128
#define BNROWS (BDIM * NPTS)   // 65536
#define EPS_DIST 1e-10f
#define EPS_BN   1e-5f

// ---------------- scratch (device globals; no allocations allowed) ----------
__device__ float g_w[BNROWS * 3];
__device__ int   g_idx[BNROWS * 3];
__device__ float g_P2[BDIM * SPTS * C1C];      // 16384 x 256  (points2 @ W1b^T)
__device__ float g_h1[BNROWS * C1C];           // 65536 x 256  (raw pre-BN h1)
__device__ float g_sum1[C1C], g_sq1[C1C], g_scale1[C1C], g_shift1[C1C];
__device__ float g_sum2[C2C], g_sq2[C2C], g_scale2[C2C], g_shift2[C2C];

// ---------------- 1. zero stat accumulators (graph replays need this) -------
__global__ void zero_stats_kernel() {
    int t = threadIdx.x;
    if (t < C1C) { g_sum1[t] = 0.f; g_sq1[t] = 0.f; }
    if (t < C2C) { g_sum2[t] = 0.f; g_sq2[t] = 0.f; }
}

// ---------------- 2. kNN(3) + inverse-distance weights ----------------------
// grid (NPTS/256, BDIM), block 256. xyz2 batch tile cached in smem as float4.
__global__ void knn_kernel(const float* __restrict__ xyz1,
                           const float* __restrict__ xyz2) {
    __shared__ float4 sp[SPTS];   // 32 KB
    const int b = blockIdx.y;
    const float* x2 = xyz2 + (size_t)b * SPTS * 3;
    for (int i = threadIdx.x; i < SPTS; i += blockDim.x)
        sp[i] = make_float4(x2[3 * i], x2[3 * i + 1], x2[3 * i + 2], 0.f);
    __syncthreads();

    const int n   = blockIdx.x * blockDim.x + threadIdx.x;
    const int row = b * NPTS + n;
    const float qx = xyz1[(size_t)row * 3 + 0];
    const float qy = xyz1[(size_t)row * 3 + 1];
    const float qz = xyz1[(size_t)row * 3 + 2];

    float d0 = 1e30f, d1 = 1e30f, d2v = 1e30f;
    int   i0 = 0,     i1 = 0,     i2 = 0;
    #pragma unroll 8
    for (int s = 0; s < SPTS; s++) {
        float4 p = sp[s];
        float dx = qx - p.x, dy = qy - p.y, dz = qz - p.z;
        float d = fmaf(dx, dx, fmaf(dy, dy, dz * dz));
        if (d < d2v) {
            if (d < d1) {
                d2v = d1; i2 = i1;
                if (d < d0) { d1 = d0; i1 = i0; d0 = d; i0 = s; }
                else        { d1 = d;  i1 = s; }
            } else { d2v = d; i2 = s; }
        }
    }
    d0  = fmaxf(d0,  EPS_DIST);
    d1  = fmaxf(d1,  EPS_DIST);
    d2v = fmaxf(d2v, EPS_DIST);
    float w0 = 1.f / d0, w1 = 1.f / d1, w2 = 1.f / d2v;
    float inv = 1.f / (w0 + w1 + w2);
    g_w[row * 3 + 0] = w0 * inv;
    g_w[row * 3 + 1] = w1 * inv;
    g_w[row * 3 + 2] = w2 * inv;
    g_idx[row * 3 + 0] = i0;
    g_idx[row * 3 + 1] = i1;
    g_idx[row * 3 + 2] = i2;
}

// ---------------- 3. P2 = points2 @ W1b^T  (M=16384, N=256, K=256) ----------
// Tiled fp32 GEMM: 64x64 block tile, 256 threads, 4x4 micro-tile, BK=16.
__global__ void gemm_p2_kernel(const float* __restrict__ points2,
                               const float* __restrict__ W1) {
    __shared__ float As[16][64], Bs[16][64];
    const int t  = threadIdx.x;
    const int tx = t & 15, ty = t >> 4;
    const int m0 = blockIdx.x * 64, n0 = blockIdx.y * 64;
    const int lr = t >> 2, lc = (t & 3) << 2;
    float acc[4][4] = {};
    for (int k0 = 0; k0 < D2C; k0 += 16) {
        float4 av = *(const float4*)(points2 + (size_t)(m0 + lr) * D2C + k0 + lc);
        float4 bv = *(const float4*)(W1 + (size_t)(n0 + lr) * (D1C + D2C) + D1C + k0 + lc);
        __syncthreads();
        As[lc+0][lr]=av.x; As[lc+1][lr]=av.y; As[lc+2][lr]=av.z; As[lc+3][lr]=av.w;
        Bs[lc+0][lr]=bv.x; Bs[lc+1][lr]=bv.y; Bs[lc+2][lr]=bv.z; Bs[lc+3][lr]=bv.w;
        __syncthreads();
        #pragma unroll
        for (int k = 0; k < 16; k++) {
            float4 a = *(const float4*)&As[k][ty << 2];
            float4 b = *(const float4*)&Bs[k][tx << 2];
            float ar[4] = {a.x, a.y, a.z, a.w};
            float br[4] = {b.x, b.y, b.z, b.w};
            #pragma unroll
            for (int i = 0; i < 4; i++)
                #pragma unroll
                for (int j = 0; j < 4; j++)
                    acc[i][j] = fmaf(ar[i], br[j], acc[i][j]);
        }
    }
    #pragma unroll
    for (int i = 0; i < 4; i++) {
        float4 o = make_float4(acc[i][0], acc[i][1], acc[i][2], acc[i][3]);
        *(float4*)(g_P2 + (size_t)(m0 + ty * 4 + i) * C1C + n0 + tx * 4) = o;
    }
}

// ---------------- 4. h1 = points1 @ W1a^T + Σ w_k · P2[idx_k] ---------------
// M=65536, N=256, K=64. Gather-add fused in epilogue (P2 is L2-resident).
__global__ void gemm1_kernel(const float* __restrict__ points1,
                             const float* __restrict__ W1) {
    __shared__ float As[16][64], Bs[16][64];
    __shared__ float sw[64 * 3];
    __shared__ int   si[64 * 3];
    const int t  = threadIdx.x;
    const int tx = t & 15, ty = t >> 4;
    const int m0 = blockIdx.x * 64, n0 = blockIdx.y * 64;
    if (t < 64) {
        int r = m0 + t;
        sw[t*3+0] = g_w[r*3+0]; sw[t*3+1] = g_w[r*3+1]; sw[t*3+2] = g_w[r*3+2];
        si[t*3+0] = g_idx[r*3+0]; si[t*3+1] = g_idx[r*3+1]; si[t*3+2] = g_idx[r*3+2];
    }
    const int lr = t >> 2, lc = (t & 3) << 2;
    float acc[4][4] = {};
    #pragma unroll
    for (int k0 = 0; k0 < D1C; k0 += 16) {
        float4 av = *(const float4*)(points1 + (size_t)(m0 + lr) * D1C + k0 + lc);
        float4 bv = *(const float4*)(W1 + (size_t)(n0 + lr) * (D1C + D2C) + k0 + lc);
        __syncthreads();
        As[lc+0][lr]=av.x; As[lc+1][lr]=av.y; As[lc+2][lr]=av.z; As[lc+3][lr]=av.w;
        Bs[lc+0][lr]=bv.x; Bs[lc+1][lr]=bv.y; Bs[lc+2][lr]=bv.z; Bs[lc+3][lr]=bv.w;
        __syncthreads();
        #pragma unroll
        for (int k = 0; k < 16; k++) {
            float4 a = *(const float4*)&As[k][ty << 2];
            float4 b = *(const float4*)&Bs[k][tx << 2];
            float ar[4] = {a.x, a.y, a.z, a.w};
            float br[4] = {b.x, b.y, b.z, b.w};
            #pragma unroll
            for (int i = 0; i < 4; i++)
                #pragma unroll
                for (int j = 0; j < 4; j++)
                    acc[i][j] = fmaf(ar[i], br[j], acc[i][j]);
        }
    }
    const int bidx = m0 / NPTS;               // 64 | NPTS, so constant per block
    const float* P2b = g_P2 + (size_t)bidx * SPTS * C1C;
    #pragma unroll
    for (int i = 0; i < 4; i++) {
        const int lr2 = ty * 4 + i;
        const int row = m0 + lr2;
        float4 add = make_float4(0.f, 0.f, 0.f, 0.f);
        #pragma unroll
        for (int k3 = 0; k3 < 3; k3++) {
            float wk = sw[lr2 * 3 + k3];
            float4 v = *(const float4*)(P2b + (size_t)si[lr2 * 3 + k3] * C1C + n0 + tx * 4);
            add.x = fmaf(wk, v.x, add.x); add.y = fmaf(wk, v.y, add.y);
            add.z = fmaf(wk, v.z, add.z); add.w = fmaf(wk, v.w, add.w);
        }
        float4 o = make_float4(acc[i][0] + add.x, acc[i][1] + add.y,
                               acc[i][2] + add.z, acc[i][3] + add.w);
        *(float4*)(g_h1 + (size_t)row * C1C + n0 + tx * 4) = o;
    }
}

// ---------------- 5./8. column stats (sum, sumsq) ---------------------------
__global__ void stats1_kernel() {     // over g_h1, C=256
    const int t  = threadIdx.x;       // col
    const int r0 = blockIdx.x * 256;
    float s = 0.f, q = 0.f;
    for (int r = 0; r < 256; r++) {
        float v = g_h1[(size_t)(r0 + r) * C1C + t];
        s += v; q = fmaf(v, v, q);
    }
    atomicAdd(&g_sum1[t], s);
    atomicAdd(&g_sq1[t], q);
}
__global__ void stats2_kernel(const float* __restrict__ H) {  // over d_out, C=128
    const int t    = threadIdx.x;
    const int col  = t & (C2C - 1);
    const int rsub = t >> 7;          // 0 or 1
    const int r0   = blockIdx.x * 256;
    float s = 0.f, q = 0.f;
    for (int r = rsub; r < 256; r += 2) {
        float v = H[(size_t)(r0 + r) * C2C + col];
        s += v; q = fmaf(v, v, q);
    }
    atomicAdd(&g_sum2[col], s);
    atomicAdd(&g_sq2[col], q);
}

// ---------------- 6./9. fold BN into scale/shift ----------------------------
__global__ void finalize_kernel(const float* __restrict__ gamma,
                                const float* __restrict__ beta, int which) {
    const int t = threadIdx.x;
    const float invM = 1.0f / (float)BNROWS;
    if (which == 0) {
        if (t < C1C) {
            float mean = g_sum1[t] * invM;
            float var  = g_sq1[t] * invM - mean * mean;
            float a    = gamma[t] * rsqrtf(var + EPS_BN);
            g_scale1[t] = a;
            g_shift1[t] = fmaf(-mean, a, beta[t]);
        }
    } else {
        if (t < C2C) {
            float mean = g_sum2[t] * invM;
            float var  = g_sq2[t] * invM - mean * mean;
            float a    = gamma[t] * rsqrtf(var + EPS_BN);
            g_scale2[t] = a;
            g_shift2[t] = fmaf(-mean, a, beta[t]);
        }
    }
}

// ---------------- 7. h2 = relu(bn1(h1)) @ W2^T  (raw into d_out) ------------
// M=65536, N=128, K=256. BN1+ReLU applied on A-tile load.
__global__ void gemm2_kernel(const float* __restrict__ W2,
                             float* __restrict__ out) {
    __shared__ float As[16][64], Bs[16][64];
    __shared__ float ss[C1C], sh[C1C];
    const int t = threadIdx.x;
    ss[t] = g_scale1[t];
    sh[t] = g_shift1[t];
    __syncthreads();
    const int tx = t & 15, ty = t >> 4;
    const int m0 = blockIdx.x * 64, n0 = blockIdx.y * 64;
    const int lr = t >> 2, lc = (t & 3) << 2;
    float acc[4][4] = {};
    for (int k0 = 0; k0 < C1C; k0 += 16) {
        float4 av = *(const float4*)(g_h1 + (size_t)(m0 + lr) * C1C + k0 + lc);
        float4 bv = *(const float4*)(W2 + (size_t)(n0 + lr) * C1C + k0 + lc);
        av.x = fmaxf(fmaf(av.x, ss[k0+lc+0], sh[k0+lc+0]), 0.f);
        av.y = fmaxf(fmaf(av.y, ss[k0+lc+1], sh[k0+lc+1]), 0.f);
        av.z = fmaxf(fmaf(av.z, ss[k0+lc+2], sh[k0+lc+2]), 0.f);
        av.w = fmaxf(fmaf(av.w, ss[k0+lc+3], sh[k0+lc+3]), 0.f);
        __syncthreads();
        As[lc+0][lr]=av.x; As[lc+1][lr]=av.y; As[lc+2][lr]=av.z; As[lc+3][lr]=av.w;
        Bs[lc+0][lr]=bv.x; Bs[lc+1][lr]=bv.y; Bs[lc+2][lr]=bv.z; Bs[lc+3][lr]=bv.w;
        __syncthreads();
        #pragma unroll
        for (int k = 0; k < 16; k++) {
            float4 a = *(const float4*)&As[k][ty << 2];
            float4 b = *(const float4*)&Bs[k][tx << 2];
            float ar[4] = {a.x, a.y, a.z, a.w};
            float br[4] = {b.x, b.y, b.z, b.w};
            #pragma unroll
            for (int i = 0; i < 4; i++)
                #pragma unroll
                for (int j = 0; j < 4; j++)
                    acc[i][j] = fmaf(ar[i], br[j], acc[i][j]);
        }
    }
    #pragma unroll
    for (int i = 0; i < 4; i++) {
        float4 o = make_float4(acc[i][0], acc[i][1], acc[i][2], acc[i][3]);
        *(float4*)(out + (size_t)(m0 + ty * 4 + i) * C2C + n0 + tx * 4) = o;
    }
}

// ---------------- 10. out = relu(bn2(out)) in place -------------------------
__global__ void apply_kernel(float* __restrict__ out) {
    const int i = blockIdx.x * blockDim.x + threadIdx.x;   // float4 index
    float4 v = ((float4*)out)[i];
    const int c = (i * 4) & (C2C - 1);
    v.x = fmaxf(fmaf(v.x, g_scale2[c + 0], g_shift2[c + 0]), 0.f);
    v.y = fmaxf(fmaf(v.y, g_scale2[c + 1], g_shift2[c + 1]), 0.f);
    v.z = fmaxf(fmaf(v.z, g_scale2[c + 2], g_shift2[c + 2]), 0.f);
    v.w = fmaxf(fmaf(v.w, g_scale2[c + 3], g_shift2[c + 3]), 0.f);
    ((float4*)out)[i] = v;
}

// ---------------- launch ----------------------------------------------------
extern "C" void kernel_launch(void* const* d_in, const int* in_sizes, int n_in,
                              void* d_out, int out_size) {
    const float* xyz1    = (const float*)d_in[0];
    const float* xyz2    = (const float*)d_in[1];
    const float* points1 = (const float*)d_in[2];
    const float* points2 = (const float*)d_in[3];
    const float* W1      = (const float*)d_in[4];
    const float* g1      = (const float*)d_in[5];
    const float* b1      = (const float*)d_in[6];
    const float* W2      = (const float*)d_in[7];
    const float* g2      = (const float*)d_in[8];
    const float* b2      = (const float*)d_in[9];
    float* out = (float*)d_out;
    (void)in_sizes; (void)n_in; (void)out_size;

    zero_stats_kernel<<<1, 256>>>();
    knn_kernel<<<dim3(NPTS / 256, BDIM), 256>>>(xyz1, xyz2);
    gemm_p2_kernel<<<dim3(BDIM * SPTS / 64, C1C / 64), 256>>>(points2, W1);
    gemm1_kernel<<<dim3(BNROWS / 64, C1C / 64), 256>>>(points1, W1);
    stats1_kernel<<<BNROWS / 256, 256>>>();
    finalize_kernel<<<1, 256>>>(g1, b1, 0);
    gemm2_kernel<<<dim3(BNROWS / 64, C2C / 64), 256>>>(W2, out);
    stats2_kernel<<<BNROWS / 256, 256>>>(out);
    finalize_kernel<<<1, 256>>>(g2, b2, 1);
    apply_kernel<<<(BNROWS * C2C / 4) / 256, 256>>>(out);
}

// round 5
// speedup vs baseline: 1.9087x; 1.9087x over previous
#include <cuda_runtime.h>
#include <cuda_bf16.h>
#include <cstdint>

// Problem constants
#define BDIM 8
#define NPTS 8192
#define SPTS 2048
#define D1C  64
#define D2C  256
#define C1C  256
#define C2C  128
#define BNROWS (BDIM * NPTS)   // 65536
#define EPS_DIST 1e-10f
#define EPS_BN   1e-5f

// ---------------- scratch (device globals; no allocations allowed) ----------
__device__ float g_w[BNROWS * 3];
__device__ int   g_idx[BNROWS * 3];
__device__ float g_P2[BDIM * SPTS * C1C];      // 16384 x 256 fp32
__device__ float g_h1[BNROWS * C1C];           // 65536 x 256 fp32 (pre-BN h1)
__device__ float g_sum1[C1C], g_sq1[C1C], g_scale1[C1C], g_shift1[C1C];
__device__ float g_sum2[C2C], g_sq2[C2C], g_scale2[C2C], g_shift2[C2C];

// bf16 split operands (hi/lo)
__device__ __nv_bfloat16 g_p1h[BNROWS * D1C],      g_p1l[BNROWS * D1C];
__device__ __nv_bfloat16 g_p2h[BDIM*SPTS * D2C],   g_p2l[BDIM*SPTS * D2C];
__device__ __nv_bfloat16 g_w1h[C1C * (D1C+D2C)],   g_w1l[C1C * (D1C+D2C)];
__device__ __nv_bfloat16 g_w2h[C2C * C1C],         g_w2l[C2C * C1C];
__device__ __nv_bfloat16 g_a1h[BNROWS * C1C],      g_a1l[BNROWS * C1C];

// ---------------- 1. zero stat accumulators ---------------------------------
__global__ void zero_stats_kernel() {
    int t = threadIdx.x;
    if (t < C1C) { g_sum1[t] = 0.f; g_sq1[t] = 0.f; }
    if (t < C2C) { g_sum2[t] = 0.f; g_sq2[t] = 0.f; }
}

// ---------------- 2. kNN(3) + inverse-distance weights ----------------------
__global__ void knn_kernel(const float* __restrict__ xyz1,
                           const float* __restrict__ xyz2) {
    __shared__ float4 sp[SPTS];   // 32 KB
    const int b = blockIdx.y;
    const float* x2 = xyz2 + (size_t)b * SPTS * 3;
    for (int i = threadIdx.x; i < SPTS; i += blockDim.x)
        sp[i] = make_float4(x2[3 * i], x2[3 * i + 1], x2[3 * i + 2], 0.f);
    __syncthreads();

    const int n   = blockIdx.x * blockDim.x + threadIdx.x;
    const int row = b * NPTS + n;
    const float qx = xyz1[(size_t)row * 3 + 0];
    const float qy = xyz1[(size_t)row * 3 + 1];
    const float qz = xyz1[(size_t)row * 3 + 2];

    float d0 = 1e30f, d1 = 1e30f, d2v = 1e30f;
    int   i0 = 0,     i1 = 0,     i2 = 0;
    #pragma unroll 8
    for (int s = 0; s < SPTS; s++) {
        float4 p = sp[s];
        float dx = qx - p.x, dy = qy - p.y, dz = qz - p.z;
        float d = fmaf(dx, dx, fmaf(dy, dy, dz * dz));
        if (d < d2v) {
            if (d < d1) {
                d2v = d1; i2 = i1;
                if (d < d0) { d1 = d0; i1 = i0; d0 = d; i0 = s; }
                else        { d1 = d;  i1 = s; }
            } else { d2v = d; i2 = s; }
        }
    }
    d0  = fmaxf(d0,  EPS_DIST);
    d1  = fmaxf(d1,  EPS_DIST);
    d2v = fmaxf(d2v, EPS_DIST);
    float w0 = 1.f / d0, w1 = 1.f / d1, w2 = 1.f / d2v;
    float inv = 1.f / (w0 + w1 + w2);
    g_w[row * 3 + 0] = w0 * inv;
    g_w[row * 3 + 1] = w1 * inv;
    g_w[row * 3 + 2] = w2 * inv;
    g_idx[row * 3 + 0] = i0;
    g_idx[row * 3 + 1] = i1;
    g_idx[row * 3 + 2] = i2;
}

// ---------------- 3. fp32 -> bf16 hi/lo split --------------------------------
__global__ void split_kernel(const float* __restrict__ src,
                             __nv_bfloat16* __restrict__ hi,
                             __nv_bfloat16* __restrict__ lo) {
    const size_t i = ((size_t)blockIdx.x * blockDim.x + threadIdx.x) * 8;
    float4 a = *(const float4*)(src + i);
    float4 b = *(const float4*)(src + i + 4);
    float x[8] = {a.x, a.y, a.z, a.w, b.x, b.y, b.z, b.w};
    __nv_bfloat16 hv[8], lv[8];
    #pragma unroll
    for (int j = 0; j < 8; j++) {
        hv[j] = __float2bfloat16(x[j]);
        lv[j] = __float2bfloat16(x[j] - __bfloat162float(hv[j]));
    }
    *(uint4*)(hi + i) = *(uint4*)hv;
    *(uint4*)(lo + i) = *(uint4*)lv;
}

// a1 = relu(bn1(h1)) -> bf16 hi/lo
__global__ void conv_a1_kernel() {
    const size_t i = ((size_t)blockIdx.x * blockDim.x + threadIdx.x) * 8;
    const int c = (int)(i & (C1C - 1));
    float4 a = *(const float4*)(g_h1 + i);
    float4 b = *(const float4*)(g_h1 + i + 4);
    float x[8] = {a.x, a.y, a.z, a.w, b.x, b.y, b.z, b.w};
    __nv_bfloat16 hv[8], lv[8];
    #pragma unroll
    for (int j = 0; j < 8; j++) {
        float v = fmaxf(fmaf(x[j], g_scale1[c + j], g_shift1[c + j]), 0.f);
        hv[j] = __float2bfloat16(v);
        lv[j] = __float2bfloat16(v - __bfloat162float(hv[j]));
    }
    *(uint4*)(g_a1h + i) = *(uint4*)hv;
    *(uint4*)(g_a1l + i) = *(uint4*)lv;
}

// ---------------- HMMA (mma.sync) split-bf16 GEMM ----------------------------
__device__ __forceinline__ void mma16816(float* c, uint32_t a0, uint32_t a1,
                                         uint32_t a2, uint32_t a3,
                                         uint32_t b0, uint32_t b1) {
    asm volatile(
        "mma.sync.aligned.m16n8k16.row.col.f32.bf16.bf16.f32 "
        "{%0,%1,%2,%3}, {%4,%5,%6,%7}, {%8,%9}, {%0,%1,%2,%3};"
        : "+f"(c[0]), "+f"(c[1]), "+f"(c[2]), "+f"(c[3])
        : "r"(a0), "r"(a1), "r"(a2), "r"(a3), "r"(b0), "r"(b1));
}

#define SROW 40   // smem row stride in bf16 (conflict-free: bank = 20g+tig perm)

// Block tile 128x128, BK=32, 8 warps (2x4), warp tile 64x32.
// EPI 0: P2 = points2 @ W1b^T          (K=256) -> g_P2
// EPI 1: h1 = points1 @ W1a^T + gather (K=64)  -> g_h1
// EPI 2: h2 = a1 @ W2^T                (K=256) -> out
template<int EPI>
__global__ void __launch_bounds__(256) gemm_mma_kernel(float* __restrict__ outp) {
    __shared__ __nv_bfloat16 sAh[128 * SROW], sAl[128 * SROW];
    __shared__ __nv_bfloat16 sBh[128 * SROW], sBl[128 * SROW];

    const int tid = threadIdx.x, wid = tid >> 5, lane = tid & 31;
    const int wm = wid >> 2, wn = wid & 3;          // warp grid 2x4
    const int g = lane >> 2, tig = lane & 3;
    const int m0 = blockIdx.x * 128, n0 = blockIdx.y * 128;

    const uint4 *A4h, *A4l, *B4h, *B4l;
    int sa8, sb8, bofs8, K;
    if (EPI == 0) {
        A4h = (const uint4*)g_p2h; A4l = (const uint4*)g_p2l; sa8 = D2C/8;
        B4h = (const uint4*)g_w1h; B4l = (const uint4*)g_w1l; sb8 = (D1C+D2C)/8;
        bofs8 = D1C/8; K = D2C;
    } else if (EPI == 1) {
        A4h = (const uint4*)g_p1h; A4l = (const uint4*)g_p1l; sa8 = D1C/8;
        B4h = (const uint4*)g_w1h; B4l = (const uint4*)g_w1l; sb8 = (D1C+D2C)/8;
        bofs8 = 0; K = D1C;
    } else {
        A4h = (const uint4*)g_a1h; A4l = (const uint4*)g_a1l; sa8 = C1C/8;
        B4h = (const uint4*)g_w2h; B4l = (const uint4*)g_w2l; sb8 = C1C/8;
        bofs8 = 0; K = C1C;
    }

    float acc[4][4][4];
    #pragma unroll
    for (int i = 0; i < 4; i++)
        #pragma unroll
        for (int j = 0; j < 4; j++)
            #pragma unroll
            for (int e = 0; e < 4; e++) acc[i][j][e] = 0.f;

    for (int k0 = 0; k0 < K; k0 += 32) {
        __syncthreads();
        const int k8 = k0 >> 3;
        #pragma unroll
        for (int u = tid; u < 512; u += 256) {
            const int row = u >> 2, kc = u & 3;
            const size_t ga = (size_t)(m0 + row) * sa8 + k8 + kc;
            const size_t gb = (size_t)(n0 + row) * sb8 + bofs8 + k8 + kc;
            const int so = row * 5 + kc;   // 40 bf16 = 5 uint4 per row
            ((uint4*)sAh)[so] = A4h[ga];
            ((uint4*)sAl)[so] = A4l[ga];
            ((uint4*)sBh)[so] = B4h[gb];
            ((uint4*)sBl)[so] = B4l[gb];
        }
        __syncthreads();

        #pragma unroll
        for (int kk = 0; kk < 32; kk += 16) {
            uint32_t ah[4][4], al[4][4];
            #pragma unroll
            for (int mi = 0; mi < 4; mi++) {
                const int r = wm * 64 + mi * 16 + g;
                const int o = r * SROW + kk + 2 * tig;
                ah[mi][0] = *(const uint32_t*)(sAh + o);
                ah[mi][1] = *(const uint32_t*)(sAh + o + 8 * SROW);
                ah[mi][2] = *(const uint32_t*)(sAh + o + 8);
                ah[mi][3] = *(const uint32_t*)(sAh + o + 8 * SROW + 8);
                al[mi][0] = *(const uint32_t*)(sAl + o);
                al[mi][1] = *(const uint32_t*)(sAl + o + 8 * SROW);
                al[mi][2] = *(const uint32_t*)(sAl + o + 8);
                al[mi][3] = *(const uint32_t*)(sAl + o + 8 * SROW + 8);
            }
            #pragma unroll
            for (int ni = 0; ni < 4; ni++) {
                const int nr = wn * 32 + ni * 8 + g;
                const int o = nr * SROW + kk + 2 * tig;
                uint32_t bh0 = *(const uint32_t*)(sBh + o);
                uint32_t bh1 = *(const uint32_t*)(sBh + o + 8);
                uint32_t bl0 = *(const uint32_t*)(sBl + o);
                uint32_t bl1 = *(const uint32_t*)(sBl + o + 8);
                #pragma unroll
                for (int mi = 0; mi < 4; mi++) {
                    mma16816(acc[mi][ni], ah[mi][0], ah[mi][1], ah[mi][2], ah[mi][3], bh0, bh1);
                    mma16816(acc[mi][ni], ah[mi][0], ah[mi][1], ah[mi][2], ah[mi][3], bl0, bl1);
                    mma16816(acc[mi][ni], al[mi][0], al[mi][1], al[mi][2], al[mi][3], bh0, bh1);
                }
            }
        }
    }

    // ---------------- epilogue ----------------
    float* dst;
    int ldo;
    if (EPI == 0)      { dst = g_P2; ldo = C1C; }
    else if (EPI == 1) { dst = g_h1; ldo = C1C; }
    else               { dst = outp; ldo = C2C; }

    const float* P2b = nullptr;
    if (EPI == 1) P2b = g_P2 + (size_t)(m0 >> 13) * SPTS * C1C;

    #pragma unroll
    for (int mi = 0; mi < 4; mi++) {
        #pragma unroll
        for (int rr = 0; rr < 2; rr++) {
            const int grow = m0 + wm * 64 + mi * 16 + g + rr * 8;
            float w0 = 0.f, w1 = 0.f, w2 = 0.f;
            const float *p0 = nullptr, *p1 = nullptr, *p2 = nullptr;
            if (EPI == 1) {
                w0 = g_w[grow * 3 + 0]; w1 = g_w[grow * 3 + 1]; w2 = g_w[grow * 3 + 2];
                p0 = P2b + (size_t)g_idx[grow * 3 + 0] * C1C;
                p1 = P2b + (size_t)g_idx[grow * 3 + 1] * C1C;
                p2 = P2b + (size_t)g_idx[grow * 3 + 2] * C1C;
            }
            #pragma unroll
            for (int ni = 0; ni < 4; ni++) {
                const int col = n0 + wn * 32 + ni * 8 + 2 * tig;
                float vx = acc[mi][ni][rr * 2 + 0];
                float vy = acc[mi][ni][rr * 2 + 1];
                if (EPI == 1) {
                    float2 q0 = *(const float2*)(p0 + col);
                    float2 q1 = *(const float2*)(p1 + col);
                    float2 q2 = *(const float2*)(p2 + col);
                    vx += w0 * q0.x + w1 * q1.x + w2 * q2.x;
                    vy += w0 * q0.y + w1 * q1.y + w2 * q2.y;
                }
                *(float2*)(dst + (size_t)grow * ldo + col) = make_float2(vx, vy);
            }
        }
    }
}

// ---------------- column stats (sum, sumsq) ----------------------------------
__global__ void stats1_kernel() {     // over g_h1, C=256
    const int t  = threadIdx.x;
    const int r0 = blockIdx.x * 256;
    float s = 0.f, q = 0.f;
    for (int r = 0; r < 256; r++) {
        float v = g_h1[(size_t)(r0 + r) * C1C + t];
        s += v; q = fmaf(v, v, q);
    }
    atomicAdd(&g_sum1[t], s);
    atomicAdd(&g_sq1[t], q);
}
__global__ void stats2_kernel(const float* __restrict__ H) {  // over d_out, C=128
    const int t    = threadIdx.x;
    const int col  = t & (C2C - 1);
    const int rsub = t >> 7;
    const int r0   = blockIdx.x * 256;
    float s = 0.f, q = 0.f;
    for (int r = rsub; r < 256; r += 2) {
        float v = H[(size_t)(r0 + r) * C2C + col];
        s += v; q = fmaf(v, v, q);
    }
    atomicAdd(&g_sum2[col], s);
    atomicAdd(&g_sq2[col], q);
}

// ---------------- fold BN into scale/shift -----------------------------------
__global__ void finalize_kernel(const float* __restrict__ gamma,
                                const float* __restrict__ beta, int which) {
    const int t = threadIdx.x;
    const float invM = 1.0f / (float)BNROWS;
    if (which == 0) {
        if (t < C1C) {
            float mean = g_sum1[t] * invM;
            float var  = g_sq1[t] * invM - mean * mean;
            float a    = gamma[t] * rsqrtf(var + EPS_BN);
            g_scale1[t] = a;
            g_shift1[t] = fmaf(-mean, a, beta[t]);
        }
    } else {
        if (t < C2C) {
            float mean = g_sum2[t] * invM;
            float var  = g_sq2[t] * invM - mean * mean;
            float a    = gamma[t] * rsqrtf(var + EPS_BN);
            g_scale2[t] = a;
            g_shift2[t] = fmaf(-mean, a, beta[t]);
        }
    }
}

// ---------------- out = relu(bn2(out)) in place ------------------------------
__global__ void apply_kernel(float* __restrict__ out) {
    const int i = blockIdx.x * blockDim.x + threadIdx.x;   // float4 index
    float4 v = ((float4*)out)[i];
    const int c = (i * 4) & (C2C - 1);
    v.x = fmaxf(fmaf(v.x, g_scale2[c + 0], g_shift2[c + 0]), 0.f);
    v.y = fmaxf(fmaf(v.y, g_scale2[c + 1], g_shift2[c + 1]), 0.f);
    v.z = fmaxf(fmaf(v.z, g_scale2[c + 2], g_shift2[c + 2]), 0.f);
    v.w = fmaxf(fmaf(v.w, g_scale2[c + 3], g_shift2[c + 3]), 0.f);
    ((float4*)out)[i] = v;
}

// ---------------- launch -----------------------------------------------------
extern "C" void kernel_launch(void* const* d_in, const int* in_sizes, int n_in,
                              void* d_out, int out_size) {
    const float* xyz1    = (const float*)d_in[0];
    const float* xyz2    = (const float*)d_in[1];
    const float* points1 = (const float*)d_in[2];
    const float* points2 = (const float*)d_in[3];
    const float* W1      = (const float*)d_in[4];
    const float* g1      = (const float*)d_in[5];
    const float* b1      = (const float*)d_in[6];
    const float* W2      = (const float*)d_in[7];
    const float* g2      = (const float*)d_in[8];
    const float* b2      = (const float*)d_in[9];
    float* out = (float*)d_out;
    (void)in_sizes; (void)n_in; (void)out_size;

    __nv_bfloat16 *p2h, *p2l, *p1h, *p1l, *w1h, *w1l, *w2h, *w2l;
    cudaGetSymbolAddress((void**)&p2h, g_p2h); cudaGetSymbolAddress((void**)&p2l, g_p2l);
    cudaGetSymbolAddress((void**)&p1h, g_p1h); cudaGetSymbolAddress((void**)&p1l, g_p1l);
    cudaGetSymbolAddress((void**)&w1h, g_w1h); cudaGetSymbolAddress((void**)&w1l, g_w1l);
    cudaGetSymbolAddress((void**)&w2h, g_w2h); cudaGetSymbolAddress((void**)&w2l, g_w2l);

    zero_stats_kernel<<<1, 256>>>();
    knn_kernel<<<dim3(NPTS / 256, BDIM), 256>>>(xyz1, xyz2);

    split_kernel<<<(BDIM*SPTS*D2C)/2048, 256>>>(points2, p2h, p2l);
    split_kernel<<<(C1C*(D1C+D2C))/2048, 256>>>(W1, w1h, w1l);
    split_kernel<<<(C2C*C1C)/2048,       256>>>(W2, w2h, w2l);
    split_kernel<<<(BNROWS*D1C)/2048,    256>>>(points1, p1h, p1l);

    gemm_mma_kernel<0><<<dim3(BDIM*SPTS/128, C1C/128), 256>>>(nullptr);
    gemm_mma_kernel<1><<<dim3(BNROWS/128,    C1C/128), 256>>>(nullptr);

    stats1_kernel<<<BNROWS / 256, 256>>>();
    finalize_kernel<<<1, 256>>>(g1, b1, 0);
    conv_a1_kernel<<<(BNROWS*C1C)/2048, 256>>>();

    gemm_mma_kernel<2><<<dim3(BNROWS/128, C2C/128), 256>>>(out);

    stats2_kernel<<<BNROWS / 256, 256>>>(out);
    finalize_kernel<<<1, 256>>>(g2, b2, 1);
    apply_kernel<<<(BNROWS * C2C / 4) / 256, 256>>>(out);
}

// round 7
// speedup vs baseline: 2.0904x; 1.0952x over previous
#include <cuda_runtime.h>
#include <cuda_bf16.h>
#include <cstdint>

// Problem constants
#define BDIM 8
#define NPTS 8192
#define SPTS 2048
#define D1C  64
#define D2C  256
#define C1C  256
#define C2C  128
#define BNROWS (BDIM * NPTS)   // 65536
#define EPS_DIST 1e-10f
#define EPS_BN   1e-5f

// ---------------- scratch (device globals; no allocations allowed) ----------
__device__ float g_w[BNROWS * 3];
__device__ int   g_idx[BNROWS * 3];
__device__ float g_P2[BDIM * SPTS * C1C];      // 16384 x 256 fp32
__device__ float g_h1[BNROWS * C1C];           // 65536 x 256 fp32 (pre-BN h1)
__device__ float g_sum1[C1C], g_sq1[C1C], g_scale1[C1C], g_shift1[C1C];
__device__ float g_sum2[C2C], g_sq2[C2C], g_scale2[C2C], g_shift2[C2C];

// bf16 split operands (hi/lo)
__device__ __nv_bfloat16 g_p1h[BNROWS * D1C],      g_p1l[BNROWS * D1C];
__device__ __nv_bfloat16 g_p2h[BDIM*SPTS * D2C],   g_p2l[BDIM*SPTS * D2C];
__device__ __nv_bfloat16 g_w1h[C1C * (D1C+D2C)],   g_w1l[C1C * (D1C+D2C)];
__device__ __nv_bfloat16 g_w2h[C2C * C1C],         g_w2l[C2C * C1C];
__device__ __nv_bfloat16 g_a1h[BNROWS * C1C],      g_a1l[BNROWS * C1C];

// ---------------- helpers ----------------------------------------------------
__device__ __forceinline__ uint32_t smem_u32(const void* p) {
    uint32_t a;
    asm("{ .reg .u64 t; cvta.to.shared.u64 t, %1; cvt.u32.u64 %0, t; }"
        : "=r"(a) : "l"(p));
    return a;
}
__device__ __forceinline__ void cpasync16(uint32_t dst, const void* src) {
    asm volatile("cp.async.cg.shared.global [%0], [%1], 16;" :: "r"(dst), "l"(src));
}
#define CP_COMMIT() asm volatile("cp.async.commit_group;" ::: "memory")
#define CP_WAIT0()  asm volatile("cp.async.wait_group 0;" ::: "memory")
#define CP_WAIT1()  asm volatile("cp.async.wait_group 1;" ::: "memory")

__device__ __forceinline__ void mma16816(float* c, uint32_t a0, uint32_t a1,
                                         uint32_t a2, uint32_t a3,
                                         uint32_t b0, uint32_t b1) {
    asm volatile(
        "mma.sync.aligned.m16n8k16.row.col.f32.bf16.bf16.f32 "
        "{%0,%1,%2,%3}, {%4,%5,%6,%7}, {%8,%9}, {%0,%1,%2,%3};"
        : "+f"(c[0]), "+f"(c[1]), "+f"(c[2]), "+f"(c[3])
        : "r"(a0), "r"(a1), "r"(a2), "r"(a3), "r"(b0), "r"(b1));
}

// ---------------- 1. zero stat accumulators ---------------------------------
__global__ void zero_stats_kernel() {
    int t = threadIdx.x;
    if (t < C1C) { g_sum1[t] = 0.f; g_sq1[t] = 0.f; }
    if (t < C2C) { g_sum2[t] = 0.f; g_sq2[t] = 0.f; }
}

// ---------------- 2. kNN(3) + inverse-distance weights ----------------------
__global__ void knn_kernel(const float* __restrict__ xyz1,
                           const float* __restrict__ xyz2) {
    __shared__ float4 sp[SPTS];   // 32 KB
    const int b = blockIdx.y;
    const float* x2 = xyz2 + (size_t)b * SPTS * 3;
    for (int i = threadIdx.x; i < SPTS; i += blockDim.x)
        sp[i] = make_float4(x2[3 * i], x2[3 * i + 1], x2[3 * i + 2], 0.f);
    __syncthreads();

    const int n   = blockIdx.x * blockDim.x + threadIdx.x;
    const int row = b * NPTS + n;
    const float qx = xyz1[(size_t)row * 3 + 0];
    const float qy = xyz1[(size_t)row * 3 + 1];
    const float qz = xyz1[(size_t)row * 3 + 2];

    float d0 = 1e30f, d1 = 1e30f, d2v = 1e30f;
    int   i0 = 0,     i1 = 0,     i2 = 0;
    #pragma unroll 8
    for (int s = 0; s < SPTS; s++) {
        float4 p = sp[s];
        float dx = qx - p.x, dy = qy - p.y, dz = qz - p.z;
        float d = fmaf(dx, dx, fmaf(dy, dy, dz * dz));
        if (d < d2v) {
            if (d < d1) {
                d2v = d1; i2 = i1;
                if (d < d0) { d1 = d0; i1 = i0; d0 = d; i0 = s; }
                else        { d1 = d;  i1 = s; }
            } else { d2v = d; i2 = s; }
        }
    }
    d0  = fmaxf(d0,  EPS_DIST);
    d1  = fmaxf(d1,  EPS_DIST);
    d2v = fmaxf(d2v, EPS_DIST);
    float w0 = 1.f / d0, w1 = 1.f / d1, w2 = 1.f / d2v;
    float inv = 1.f / (w0 + w1 + w2);
    g_w[row * 3 + 0] = w0 * inv;
    g_w[row * 3 + 1] = w1 * inv;
    g_w[row * 3 + 2] = w2 * inv;
    g_idx[row * 3 + 0] = i0;
    g_idx[row * 3 + 1] = i1;
    g_idx[row * 3 + 2] = i2;
}

// ---------------- 3. fp32 -> bf16 hi/lo split --------------------------------
__global__ void split_kernel(const float* __restrict__ src,
                             __nv_bfloat16* __restrict__ hi,
                             __nv_bfloat16* __restrict__ lo) {
    const size_t i = ((size_t)blockIdx.x * blockDim.x + threadIdx.x) * 8;
    float4 a = *(const float4*)(src + i);
    float4 b = *(const float4*)(src + i + 4);
    float x[8] = {a.x, a.y, a.z, a.w, b.x, b.y, b.z, b.w};
    __nv_bfloat16 hv[8], lv[8];
    #pragma unroll
    for (int j = 0; j < 8; j++) {
        hv[j] = __float2bfloat16(x[j]);
        lv[j] = __float2bfloat16(x[j] - __bfloat162float(hv[j]));
    }
    *(uint4*)(hi + i) = *(uint4*)hv;
    *(uint4*)(lo + i) = *(uint4*)lv;
}

// a1 = relu(bn1(h1)) -> bf16 hi/lo
__global__ void conv_a1_kernel() {
    const size_t i = ((size_t)blockIdx.x * blockDim.x + threadIdx.x) * 8;
    const int c = (int)(i & (C1C - 1));
    float4 a = *(const float4*)(g_h1 + i);
    float4 b = *(const float4*)(g_h1 + i + 4);
    float x[8] = {a.x, a.y, a.z, a.w, b.x, b.y, b.z, b.w};
    __nv_bfloat16 hv[8], lv[8];
    #pragma unroll
    for (int j = 0; j < 8; j++) {
        float v = fmaxf(fmaf(x[j], g_scale1[c + j], g_shift1[c + j]), 0.f);
        hv[j] = __float2bfloat16(v);
        lv[j] = __float2bfloat16(v - __bfloat162float(hv[j]));
    }
    *(uint4*)(g_a1h + i) = *(uint4*)hv;
    *(uint4*)(g_a1l + i) = *(uint4*)lv;
}

// ---------------- HMMA split-bf16 GEMM, 2-stage cp.async pipeline ------------
#define SROW 40            // smem row stride in bf16 (conflict-free)
#define STG_BYTES 40960    // 4 tiles x 128 x 40 x 2B per stage
#define SMEM_GEMM (2 * STG_BYTES)

// Block tile 128x128, BK=32, 8 warps (2x4), warp tile 64x32.
template<int EPI>
__global__ void __launch_bounds__(256) gemm_mma_kernel(float* __restrict__ outp) {
    extern __shared__ char dsm[];
    const int tid = threadIdx.x, wid = tid >> 5, lane = tid & 31;
    const int wm = wid >> 2, wn = wid & 3;          // warp grid 2x4
    const int g = lane >> 2, tig = lane & 3;
    const int m0 = blockIdx.x * 128, n0 = blockIdx.y * 128;

    const uint4 *A4h, *A4l, *B4h, *B4l;
    int sa8, sb8, bofs8, K;
    if (EPI == 0) {
        A4h = (const uint4*)g_p2h; A4l = (const uint4*)g_p2l; sa8 = D2C/8;
        B4h = (const uint4*)g_w1h; B4l = (const uint4*)g_w1l; sb8 = (D1C+D2C)/8;
        bofs8 = D1C/8; K = D2C;
    } else if (EPI == 1) {
        A4h = (const uint4*)g_p1h; A4l = (const uint4*)g_p1l; sa8 = D1C/8;
        B4h = (const uint4*)g_w1h; B4l = (const uint4*)g_w1l; sb8 = (D1C+D2C)/8;
        bofs8 = 0; K = D1C;
    } else {
        A4h = (const uint4*)g_a1h; A4l = (const uint4*)g_a1l; sa8 = C1C/8;
        B4h = (const uint4*)g_w2h; B4l = (const uint4*)g_w2l; sb8 = C1C/8;
        bofs8 = 0; K = C1C;
    }
    const int KB = K >> 5;
    const uint32_t sbase = smem_u32(dsm);

    auto load_stage = [&](int st, int k8) {
        const uint32_t sa = sbase + st * STG_BYTES;
        #pragma unroll
        for (int u = tid; u < 512; u += 256) {
            const int row = u >> 2, kc = u & 3;
            const size_t ga = (size_t)(m0 + row) * sa8 + k8 + kc;
            const size_t gb = (size_t)(n0 + row) * sb8 + bofs8 + k8 + kc;
            const uint32_t so = (uint32_t)(row * 5 + kc) * 16;
            cpasync16(sa + so,         A4h + ga);
            cpasync16(sa + 10240 + so, A4l + ga);
            cpasync16(sa + 20480 + so, B4h + gb);
            cpasync16(sa + 30720 + so, B4l + gb);
        }
    };

    float acc[4][4][4];
    #pragma unroll
    for (int i = 0; i < 4; i++)
        #pragma unroll
        for (int j = 0; j < 4; j++)
            #pragma unroll
            for (int e = 0; e < 4; e++) acc[i][j][e] = 0.f;

    load_stage(0, 0);
    CP_COMMIT();

    for (int kb = 0; kb < KB; kb++) {
        if (kb + 1 < KB) {
            load_stage((kb + 1) & 1, (kb + 1) * 4);
            CP_COMMIT();
            CP_WAIT1();
        } else {
            CP_WAIT0();
        }
        __syncthreads();

        const __nv_bfloat16* sAh = (const __nv_bfloat16*)(dsm + (kb & 1) * STG_BYTES);
        const __nv_bfloat16* sAl = sAh + 5120;
        const __nv_bfloat16* sBh = sAh + 10240;
        const __nv_bfloat16* sBl = sAh + 15360;

        #pragma unroll
        for (int kk = 0; kk < 32; kk += 16) {
            uint32_t ah[4][4], al[4][4];
            #pragma unroll
            for (int mi = 0; mi < 4; mi++) {
                const int r = wm * 64 + mi * 16 + g;
                const int o = r * SROW + kk + 2 * tig;
                ah[mi][0] = *(const uint32_t*)(sAh + o);
                ah[mi][1] = *(const uint32_t*)(sAh + o + 8 * SROW);
                ah[mi][2] = *(const uint32_t*)(sAh + o + 8);
                ah[mi][3] = *(const uint32_t*)(sAh + o + 8 * SROW + 8);
                al[mi][0] = *(const uint32_t*)(sAl + o);
                al[mi][1] = *(const uint32_t*)(sAl + o + 8 * SROW);
                al[mi][2] = *(const uint32_t*)(sAl + o + 8);
                al[mi][3] = *(const uint32_t*)(sAl + o + 8 * SROW + 8);
            }
            #pragma unroll
            for (int ni = 0; ni < 4; ni++) {
                const int nr = wn * 32 + ni * 8 + g;
                const int o = nr * SROW + kk + 2 * tig;
                uint32_t bh0 = *(const uint32_t*)(sBh + o);
                uint32_t bh1 = *(const uint32_t*)(sBh + o + 8);
                uint32_t bl0 = *(const uint32_t*)(sBl + o);
                uint32_t bl1 = *(const uint32_t*)(sBl + o + 8);
                #pragma unroll
                for (int mi = 0; mi < 4; mi++) {
                    mma16816(acc[mi][ni], ah[mi][0], ah[mi][1], ah[mi][2], ah[mi][3], bh0, bh1);
                    mma16816(acc[mi][ni], ah[mi][0], ah[mi][1], ah[mi][2], ah[mi][3], bl0, bl1);
                    mma16816(acc[mi][ni], al[mi][0], al[mi][1], al[mi][2], al[mi][3], bh0, bh1);
                }
            }
        }
        __syncthreads();
    }

    // ---------------- epilogue ----------------
    float* dst;
    int ldo;
    if (EPI == 0)      { dst = g_P2; ldo = C1C; }
    else if (EPI == 1) { dst = g_h1; ldo = C1C; }
    else               { dst = outp; ldo = C2C; }

    const float* P2b = nullptr;
    if (EPI == 1) P2b = g_P2 + (size_t)(m0 >> 13) * SPTS * C1C;

    #pragma unroll
    for (int mi = 0; mi < 4; mi++) {
        #pragma unroll
        for (int rr = 0; rr < 2; rr++) {
            const int grow = m0 + wm * 64 + mi * 16 + g + rr * 8;
            float w0 = 0.f, w1 = 0.f, w2 = 0.f;
            const float *p0 = nullptr, *p1 = nullptr, *p2 = nullptr;
            if (EPI == 1) {
                w0 = g_w[grow * 3 + 0]; w1 = g_w[grow * 3 + 1]; w2 = g_w[grow * 3 + 2];
                p0 = P2b + (size_t)g_idx[grow * 3 + 0] * C1C;
                p1 = P2b + (size_t)g_idx[grow * 3 + 1] * C1C;
                p2 = P2b + (size_t)g_idx[grow * 3 + 2] * C1C;
            }
            #pragma unroll
            for (int ni = 0; ni < 4; ni++) {
                const int col = n0 + wn * 32 + ni * 8 + 2 * tig;
                float vx = acc[mi][ni][rr * 2 + 0];
                float vy = acc[mi][ni][rr * 2 + 1];
                if (EPI == 1) {
                    float2 q0 = *(const float2*)(p0 + col);
                    float2 q1 = *(const float2*)(p1 + col);
                    float2 q2 = *(const float2*)(p2 + col);
                    vx += w0 * q0.x + w1 * q1.x + w2 * q2.x;
                    vy += w0 * q0.y + w1 * q1.y + w2 * q2.y;
                }
                *(float2*)(dst + (size_t)grow * ldo + col) = make_float2(vx, vy);
            }
        }
    }
}

// ---------------- column stats (sum, sumsq) ----------------------------------
__global__ void stats1_kernel() {     // over g_h1, C=256
    const int t  = threadIdx.x;
    const int r0 = blockIdx.x * 256;
    float s = 0.f, q = 0.f;
    for (int r = 0; r < 256; r++) {
        float v = g_h1[(size_t)(r0 + r) * C1C + t];
        s += v; q = fmaf(v, v, q);
    }
    atomicAdd(&g_sum1[t], s);
    atomicAdd(&g_sq1[t], q);
}
__global__ void stats2_kernel(const float* __restrict__ H) {  // over d_out, C=128
    const int t    = threadIdx.x;
    const int col  = t & (C2C - 1);
    const int rsub = t >> 7;
    const int r0   = blockIdx.x * 256;
    float s = 0.f, q = 0.f;
    for (int r = rsub; r < 256; r += 2) {
        float v = H[(size_t)(r0 + r) * C2C + col];
        s += v; q = fmaf(v, v, q);
    }
    atomicAdd(&g_sum2[col], s);
    atomicAdd(&g_sq2[col], q);
}

// ---------------- fold BN into scale/shift -----------------------------------
__global__ void finalize_kernel(const float* __restrict__ gamma,
                                const float* __restrict__ beta, int which) {
    const int t = threadIdx.x;
    const float invM = 1.0f / (float)BNROWS;
    if (which == 0) {
        if (t < C1C) {
            float mean = g_sum1[t] * invM;
            float var  = g_sq1[t] * invM - mean * mean;
            float a    = gamma[t] * rsqrtf(var + EPS_BN);
            g_scale1[t] = a;
            g_shift1[t] = fmaf(-mean, a, beta[t]);
        }
    } else {
        if (t < C2C) {
            float mean = g_sum2[t] * invM;
            float var  = g_sq2[t] * invM - mean * mean;
            float a    = gamma[t] * rsqrtf(var + EPS_BN);
            g_scale2[t] = a;
            g_shift2[t] = fmaf(-mean, a, beta[t]);
        }
    }
}

// ---------------- out = relu(bn2(out)) in place ------------------------------
__global__ void apply_kernel(float* __restrict__ out) {
    const int i = blockIdx.x * blockDim.x + threadIdx.x;   // float4 index
    float4 v = ((float4*)out)[i];
    const int c = (i * 4) & (C2C - 1);
    v.x = fmaxf(fmaf(v.x, g_scale2[c + 0], g_shift2[c + 0]), 0.f);
    v.y = fmaxf(fmaf(v.y, g_scale2[c + 1], g_shift2[c + 1]), 0.f);
    v.z = fmaxf(fmaf(v.z, g_scale2[c + 2], g_shift2[c + 2]), 0.f);
    v.w = fmaxf(fmaf(v.w, g_scale2[c + 3], g_shift2[c + 3]), 0.f);
    ((float4*)out)[i] = v;
}

// ---------------- launch -----------------------------------------------------
extern "C" void kernel_launch(void* const* d_in, const int* in_sizes, int n_in,
                              void* d_out, int out_size) {
    const float* xyz1    = (const float*)d_in[0];
    const float* xyz2    = (const float*)d_in[1];
    const float* points1 = (const float*)d_in[2];
    const float* points2 = (const float*)d_in[3];
    const float* W1      = (const float*)d_in[4];
    const float* g1      = (const float*)d_in[5];
    const float* b1      = (const float*)d_in[6];
    const float* W2      = (const float*)d_in[7];
    const float* g2      = (const float*)d_in[8];
    const float* b2      = (const float*)d_in[9];
    float* out = (float*)d_out;
    (void)in_sizes; (void)n_in; (void)out_size;

    cudaFuncSetAttribute(gemm_mma_kernel<0>, cudaFuncAttributeMaxDynamicSharedMemorySize, SMEM_GEMM);
    cudaFuncSetAttribute(gemm_mma_kernel<1>, cudaFuncAttributeMaxDynamicSharedMemorySize, SMEM_GEMM);
    cudaFuncSetAttribute(gemm_mma_kernel<2>, cudaFuncAttributeMaxDynamicSharedMemorySize, SMEM_GEMM);

    __nv_bfloat16 *p2h, *p2l, *p1h, *p1l, *w1h, *w1l, *w2h, *w2l;
    cudaGetSymbolAddress((void**)&p2h, g_p2h); cudaGetSymbolAddress((void**)&p2l, g_p2l);
    cudaGetSymbolAddress((void**)&p1h, g_p1h); cudaGetSymbolAddress((void**)&p1l, g_p1l);
    cudaGetSymbolAddress((void**)&w1h, g_w1h); cudaGetSymbolAddress((void**)&w1l, g_w1l);
    cudaGetSymbolAddress((void**)&w2h, g_w2h); cudaGetSymbolAddress((void**)&w2l, g_w2l);

    // order chosen so ncu (-s 5 -c 1) profiles gemm_mma_kernel<0> next round
    zero_stats_kernel<<<1, 256>>>();                                        // 0
    split_kernel<<<(BDIM*SPTS*D2C)/2048, 256>>>(points2, p2h, p2l);         // 1
    split_kernel<<<(C1C*(D1C+D2C))/2048, 256>>>(W1, w1h, w1l);              // 2
    split_kernel<<<(C2C*C1C)/2048,       256>>>(W2, w2h, w2l);              // 3
    split_kernel<<<(BNROWS*D1C)/2048,    256>>>(points1, p1h, p1l);         // 4
    gemm_mma_kernel<0><<<dim3(BDIM*SPTS/128, C1C/128), 256, SMEM_GEMM>>>(nullptr); // 5
    knn_kernel<<<dim3(NPTS / 256, BDIM), 256>>>(xyz1, xyz2);                // 6
    gemm_mma_kernel<1><<<dim3(BNROWS/128,    C1C/128), 256, SMEM_GEMM>>>(nullptr); // 7
    stats1_kernel<<<BNROWS / 256, 256>>>();                                 // 8
    finalize_kernel<<<1, 256>>>(g1, b1, 0);                                 // 9
    conv_a1_kernel<<<(BNROWS*C1C)/2048, 256>>>();                           // 10
    gemm_mma_kernel<2><<<dim3(BNROWS/128, C2C/128), 256, SMEM_GEMM>>>(out); // 11
    stats2_kernel<<<BNROWS / 256, 256>>>(out);                              // 12
    finalize_kernel<<<1, 256>>>(g2, b2, 1);                                 // 13
    apply_kernel<<<(BNROWS * C2C / 4) / 256, 256>>>(out);                   // 14
}

// round 10
// speedup vs baseline: 2.2055x; 1.0550x over previous
#include <cuda_runtime.h>
#include <cuda_bf16.h>
#include <cstdint>

// Problem constants
#define BDIM 8
#define NPTS 8192
#define SPTS 2048
#define D1C  64
#define D2C  256
#define C1C  256
#define C2C  128
#define BNROWS (BDIM * NPTS)   // 65536
#define EPS_DIST 1e-10f
#define EPS_BN   1e-5f

// ---------------- scratch (device globals; no allocations allowed) ----------
__device__ float g_w[BNROWS * 3];
__device__ int   g_idx[BNROWS * 3];
__device__ float g_P2[BDIM * SPTS * C1C];      // 16384 x 256 fp32
__device__ float g_h1[BNROWS * C1C];           // 65536 x 256 fp32 (pre-BN h1)
__device__ float g_sum1[C1C], g_sq1[C1C], g_scale1[C1C], g_shift1[C1C];
__device__ float g_sum2[C2C], g_sq2[C2C], g_scale2[C2C], g_shift2[C2C];

// bf16 split operands (hi/lo)
__device__ __nv_bfloat16 g_p1h[BNROWS * D1C],      g_p1l[BNROWS * D1C];
__device__ __nv_bfloat16 g_p2h[BDIM*SPTS * D2C],   g_p2l[BDIM*SPTS * D2C];
__device__ __nv_bfloat16 g_w1h[C1C * (D1C+D2C)],   g_w1l[C1C * (D1C+D2C)];
__device__ __nv_bfloat16 g_w2h[C2C * C1C],         g_w2l[C2C * C1C];
__device__ __nv_bfloat16 g_a1h[BNROWS * C1C],      g_a1l[BNROWS * C1C];

// ---------------- helpers ----------------------------------------------------
__device__ __forceinline__ uint32_t smem_u32(const void* p) {
    uint32_t a;
    asm("{ .reg .u64 t; cvta.to.shared.u64 t, %1; cvt.u32.u64 %0, t; }"
        : "=r"(a) : "l"(p));
    return a;
}
__device__ __forceinline__ void cpasync16(uint32_t dst, const void* src) {
    asm volatile("cp.async.cg.shared.global [%0], [%1], 16;" :: "r"(dst), "l"(src));
}
#define CP_COMMIT() asm volatile("cp.async.commit_group;" ::: "memory")
#define CP_WAIT0()  asm volatile("cp.async.wait_group 0;" ::: "memory")
#define CP_WAIT1()  asm volatile("cp.async.wait_group 1;" ::: "memory")

__device__ __forceinline__ void mma16816(float* c, uint32_t a0, uint32_t a1,
                                         uint32_t a2, uint32_t a3,
                                         uint32_t b0, uint32_t b1) {
    asm volatile(
        "mma.sync.aligned.m16n8k16.row.col.f32.bf16.bf16.f32 "
        "{%0,%1,%2,%3}, {%4,%5,%6,%7}, {%8,%9}, {%0,%1,%2,%3};"
        : "+f"(c[0]), "+f"(c[1]), "+f"(c[2]), "+f"(c[3])
        : "r"(a0), "r"(a1), "r"(a2), "r"(a3), "r"(b0), "r"(b1));
}

// ---------------- prep: all fp32->bf16 hi/lo splits + stat zeroing ----------
__device__ __forceinline__ void split8(const float* __restrict__ src,
                                       __nv_bfloat16* __restrict__ hi,
                                       __nv_bfloat16* __restrict__ lo,
                                       int lb, int t) {
    const size_t i = ((size_t)lb * 256 + t) * 8;
    float4 a = *(const float4*)(src + i);
    float4 b = *(const float4*)(src + i + 4);
    float x[8] = {a.x, a.y, a.z, a.w, b.x, b.y, b.z, b.w};
    __nv_bfloat16 hv[8], lv[8];
    #pragma unroll
    for (int j = 0; j < 8; j++) {
        hv[j] = __float2bfloat16(x[j]);
        lv[j] = __float2bfloat16(x[j] - __bfloat162float(hv[j]));
    }
    *(uint4*)(hi + i) = *(uint4*)hv;
    *(uint4*)(lo + i) = *(uint4*)lv;
}

__global__ void prep_kernel(const float* __restrict__ points2,
                            const float* __restrict__ points1,
                            const float* __restrict__ W1,
                            const float* __restrict__ W2) {
    const int b = blockIdx.x, t = threadIdx.x;
    if (b < 2048)       split8(points2, g_p2h, g_p2l, b, t);
    else if (b < 4096)  split8(points1, g_p1h, g_p1l, b - 2048, t);
    else if (b < 4136)  split8(W1, g_w1h, g_w1l, b - 4096, t);
    else if (b < 4152)  split8(W2, g_w2h, g_w2l, b - 4136, t);
    else {
        if (t < C1C) { g_sum1[t] = 0.f; g_sq1[t] = 0.f; }
        if (t < C2C) { g_sum2[t] = 0.f; g_sq2[t] = 0.f; }
    }
}

// ---------------- kNN(3) + inverse-distance weights --------------------------
__global__ void knn_kernel(const float* __restrict__ xyz1,
                           const float* __restrict__ xyz2) {
    __shared__ float4 sp[SPTS];   // 32 KB
    const int b = blockIdx.y;
    const float* x2 = xyz2 + (size_t)b * SPTS * 3;
    for (int i = threadIdx.x; i < SPTS; i += blockDim.x)
        sp[i] = make_float4(x2[3 * i], x2[3 * i + 1], x2[3 * i + 2], 0.f);
    __syncthreads();

    const int n   = blockIdx.x * blockDim.x + threadIdx.x;
    const int row = b * NPTS + n;
    const float qx = xyz1[(size_t)row * 3 + 0];
    const float qy = xyz1[(size_t)row * 3 + 1];
    const float qz = xyz1[(size_t)row * 3 + 2];

    float d0 = 1e30f, d1 = 1e30f, d2v = 1e30f;
    int   i0 = 0,     i1 = 0,     i2 = 0;
    #pragma unroll 8
    for (int s = 0; s < SPTS; s++) {
        float4 p = sp[s];
        float dx = qx - p.x, dy = qy - p.y, dz = qz - p.z;
        float d = fmaf(dx, dx, fmaf(dy, dy, dz * dz));
        if (d < d2v) {
            if (d < d1) {
                d2v = d1; i2 = i1;
                if (d < d0) { d1 = d0; i1 = i0; d0 = d; i0 = s; }
                else        { d1 = d;  i1 = s; }
            } else { d2v = d; i2 = s; }
        }
    }
    d0  = fmaxf(d0,  EPS_DIST);
    d1  = fmaxf(d1,  EPS_DIST);
    d2v = fmaxf(d2v, EPS_DIST);
    float w0 = 1.f / d0, w1 = 1.f / d1, w2 = 1.f / d2v;
    float inv = 1.f / (w0 + w1 + w2);
    g_w[row * 3 + 0] = w0 * inv;
    g_w[row * 3 + 1] = w1 * inv;
    g_w[row * 3 + 2] = w2 * inv;
    g_idx[row * 3 + 0] = i0;
    g_idx[row * 3 + 1] = i1;
    g_idx[row * 3 + 2] = i2;
}

// a1 = relu(bn1(h1)) -> bf16 hi/lo
__global__ void conv_a1_kernel() {
    const size_t i = ((size_t)blockIdx.x * blockDim.x + threadIdx.x) * 8;
    const int c = (int)(i & (C1C - 1));
    float4 a = *(const float4*)(g_h1 + i);
    float4 b = *(const float4*)(g_h1 + i + 4);
    float x[8] = {a.x, a.y, a.z, a.w, b.x, b.y, b.z, b.w};
    __nv_bfloat16 hv[8], lv[8];
    #pragma unroll
    for (int j = 0; j < 8; j++) {
        float v = fmaxf(fmaf(x[j], g_scale1[c + j], g_shift1[c + j]), 0.f);
        hv[j] = __float2bfloat16(v);
        lv[j] = __float2bfloat16(v - __bfloat162float(hv[j]));
    }
    *(uint4*)(g_a1h + i) = *(uint4*)hv;
    *(uint4*)(g_a1l + i) = *(uint4*)lv;
}

// ---------------- HMMA split-bf16 GEMM, 2-stage cp.async pipeline ------------
#define SROW 40            // smem row stride in bf16 (conflict-free)
#define STG_BYTES 40960    // 4 tiles x 128 x 40 x 2B per stage
#define SMEM_GEMM (2 * STG_BYTES)

// Block tile 128x128, BK=32, 8 warps (2x4), warp tile 64x32.
// EPI 0: P2 = points2 @ W1b^T          -> g_P2
// EPI 1: h1 = points1 @ W1a^T + gather -> g_h1   (+ fused BN1 stats)
// EPI 2: h2 = a1 @ W2^T                -> out    (+ fused BN2 stats)
template<int EPI>
__global__ void __launch_bounds__(256) gemm_mma_kernel(float* __restrict__ outp) {
    extern __shared__ char dsm[];
    const int tid = threadIdx.x, wid = tid >> 5, lane = tid & 31;
    const int wm = wid >> 2, wn = wid & 3;          // warp grid 2x4
    const int g = lane >> 2, tig = lane & 3;
    const int m0 = blockIdx.x * 128, n0 = blockIdx.y * 128;

    const uint4 *A4h, *A4l, *B4h, *B4l;
    int sa8, sb8, bofs8, K;
    if (EPI == 0) {
        A4h = (const uint4*)g_p2h; A4l = (const uint4*)g_p2l; sa8 = D2C/8;
        B4h = (const uint4*)g_w1h; B4l = (const uint4*)g_w1l; sb8 = (D1C+D2C)/8;
        bofs8 = D1C/8; K = D2C;
    } else if (EPI == 1) {
        A4h = (const uint4*)g_p1h; A4l = (const uint4*)g_p1l; sa8 = D1C/8;
        B4h = (const uint4*)g_w1h; B4l = (const uint4*)g_w1l; sb8 = (D1C+D2C)/8;
        bofs8 = 0; K = D1C;
    } else {
        A4h = (const uint4*)g_a1h; A4l = (const uint4*)g_a1l; sa8 = C1C/8;
        B4h = (const uint4*)g_w2h; B4l = (const uint4*)g_w2l; sb8 = C1C/8;
        bofs8 = 0; K = C1C;
    }
    const int KB = K >> 5;
    const uint32_t sbase = smem_u32(dsm);

    auto load_stage = [&](int st, int k8) {
        const uint32_t sa = sbase + st * STG_BYTES;
        #pragma unroll
        for (int u = tid; u < 512; u += 256) {
            const int row = u >> 2, kc = u & 3;
            const size_t ga = (size_t)(m0 + row) * sa8 + k8 + kc;
            const size_t gb = (size_t)(n0 + row) * sb8 + bofs8 + k8 + kc;
            const uint32_t so = (uint32_t)(row * 5 + kc) * 16;
            cpasync16(sa + so,         A4h + ga);
            cpasync16(sa + 10240 + so, A4l + ga);
            cpasync16(sa + 20480 + so, B4h + gb);
            cpasync16(sa + 30720 + so, B4l + gb);
        }
    };

    float acc[4][4][4];
    #pragma unroll
    for (int i = 0; i < 4; i++)
        #pragma unroll
        for (int j = 0; j < 4; j++)
            #pragma unroll
            for (int e = 0; e < 4; e++) acc[i][j][e] = 0.f;

    load_stage(0, 0);
    CP_COMMIT();

    for (int kb = 0; kb < KB; kb++) {
        if (kb + 1 < KB) {
            load_stage((kb + 1) & 1, (kb + 1) * 4);
            CP_COMMIT();
            CP_WAIT1();
        } else {
            CP_WAIT0();
        }
        __syncthreads();

        const __nv_bfloat16* sAh = (const __nv_bfloat16*)(dsm + (kb & 1) * STG_BYTES);
        const __nv_bfloat16* sAl = sAh + 5120;
        const __nv_bfloat16* sBh = sAh + 10240;
        const __nv_bfloat16* sBl = sAh + 15360;

        #pragma unroll
        for (int kk = 0; kk < 32; kk += 16) {
            uint32_t ah[4][4], al[4][4];
            #pragma unroll
            for (int mi = 0; mi < 4; mi++) {
                const int r = wm * 64 + mi * 16 + g;
                const int o = r * SROW + kk + 2 * tig;
                ah[mi][0] = *(const uint32_t*)(sAh + o);
                ah[mi][1] = *(const uint32_t*)(sAh + o + 8 * SROW);
                ah[mi][2] = *(const uint32_t*)(sAh + o + 8);
                ah[mi][3] = *(const uint32_t*)(sAh + o + 8 * SROW + 8);
                al[mi][0] = *(const uint32_t*)(sAl + o);
                al[mi][1] = *(const uint32_t*)(sAl + o + 8 * SROW);
                al[mi][2] = *(const uint32_t*)(sAl + o + 8);
                al[mi][3] = *(const uint32_t*)(sAl + o + 8 * SROW + 8);
            }
            #pragma unroll
            for (int ni = 0; ni < 4; ni++) {
                const int nr = wn * 32 + ni * 8 + g;
                const int o = nr * SROW + kk + 2 * tig;
                uint32_t bh0 = *(const uint32_t*)(sBh + o);
                uint32_t bh1 = *(const uint32_t*)(sBh + o + 8);
                uint32_t bl0 = *(const uint32_t*)(sBl + o);
                uint32_t bl1 = *(const uint32_t*)(sBl + o + 8);
                #pragma unroll
                for (int mi = 0; mi < 4; mi++) {
                    mma16816(acc[mi][ni], ah[mi][0], ah[mi][1], ah[mi][2], ah[mi][3], bh0, bh1);
                    mma16816(acc[mi][ni], ah[mi][0], ah[mi][1], ah[mi][2], ah[mi][3], bl0, bl1);
                    mma16816(acc[mi][ni], al[mi][0], al[mi][1], al[mi][2], al[mi][3], bh0, bh1);
                }
            }
        }
        __syncthreads();
    }

    // ---------------- epilogue ----------------
    float* dst;
    int ldo;
    if (EPI == 0)      { dst = g_P2; ldo = C1C; }
    else if (EPI == 1) { dst = g_h1; ldo = C1C; }
    else               { dst = outp; ldo = C2C; }

    const float* P2b = nullptr;
    if (EPI == 1) P2b = g_P2 + (size_t)(m0 >> 13) * SPTS * C1C;

    float scol[8], qcol[8];   // fused BN stats partials (EPI 1/2)
    #pragma unroll
    for (int j = 0; j < 8; j++) { scol[j] = 0.f; qcol[j] = 0.f; }

    #pragma unroll
    for (int mi = 0; mi < 4; mi++) {
        #pragma unroll
        for (int rr = 0; rr < 2; rr++) {
            const int grow = m0 + wm * 64 + mi * 16 + g + rr * 8;
            float w0 = 0.f, w1 = 0.f, w2 = 0.f;
            const float *p0 = nullptr, *p1 = nullptr, *p2 = nullptr;
            if (EPI == 1) {
                w0 = g_w[grow * 3 + 0]; w1 = g_w[grow * 3 + 1]; w2 = g_w[grow * 3 + 2];
                p0 = P2b + (size_t)g_idx[grow * 3 + 0] * C1C;
                p1 = P2b + (size_t)g_idx[grow * 3 + 1] * C1C;
                p2 = P2b + (size_t)g_idx[grow * 3 + 2] * C1C;
            }
            #pragma unroll
            for (int ni = 0; ni < 4; ni++) {
                const int col = n0 + wn * 32 + ni * 8 + 2 * tig;
                float vx = acc[mi][ni][rr * 2 + 0];
                float vy = acc[mi][ni][rr * 2 + 1];
                if (EPI == 1) {
                    float2 q0 = *(const float2*)(p0 + col);
                    float2 q1 = *(const float2*)(p1 + col);
                    float2 q2 = *(const float2*)(p2 + col);
                    vx += w0 * q0.x + w1 * q1.x + w2 * q2.x;
                    vy += w0 * q0.y + w1 * q1.y + w2 * q2.y;
                }
                if (EPI != 0) {
                    scol[ni * 2 + 0] += vx; qcol[ni * 2 + 0] = fmaf(vx, vx, qcol[ni * 2 + 0]);
                    scol[ni * 2 + 1] += vy; qcol[ni * 2 + 1] = fmaf(vy, vy, qcol[ni * 2 + 1]);
                }
                *(float2*)(dst + (size_t)grow * ldo + col) = make_float2(vx, vy);
            }
        }
    }

    if (EPI != 0) {
        // reduce over g (lanes stride 4): xor 16/8/4 fold the 8 g-values
        #pragma unroll
        for (int j = 0; j < 8; j++) {
            #pragma unroll
            for (int m = 16; m >= 4; m >>= 1) {
                scol[j] += __shfl_xor_sync(0xffffffffu, scol[j], m);
                qcol[j] += __shfl_xor_sync(0xffffffffu, qcol[j], m);
            }
        }
        if (g == 0) {
            float* gs = (EPI == 1) ? g_sum1 : g_sum2;
            float* gq = (EPI == 1) ? g_sq1  : g_sq2;
            #pragma unroll
            for (int j = 0; j < 8; j++) {
                const int col = n0 + wn * 32 + (j >> 1) * 8 + 2 * tig + (j & 1);
                atomicAdd(&gs[col], scol[j]);
                atomicAdd(&gq[col], qcol[j]);
            }
        }
    }
}

// ---------------- fold BN into scale/shift -----------------------------------
__global__ void finalize_kernel(const float* __restrict__ gamma,
                                const float* __restrict__ beta, int which) {
    const int t = threadIdx.x;
    const float invM = 1.0f / (float)BNROWS;
    if (which == 0) {
        if (t < C1C) {
            float mean = g_sum1[t] * invM;
            float var  = g_sq1[t] * invM - mean * mean;
            float a    = gamma[t] * rsqrtf(var + EPS_BN);
            g_scale1[t] = a;
            g_shift1[t] = fmaf(-mean, a, beta[t]);
        }
    } else {
        if (t < C2C) {
            float mean = g_sum2[t] * invM;
            float var  = g_sq2[t] * invM - mean * mean;
            float a    = gamma[t] * rsqrtf(var + EPS_BN);
            g_scale2[t] = a;
            g_shift2[t] = fmaf(-mean, a, beta[t]);
        }
    }
}

// ---------------- out = relu(bn2(out)) in place ------------------------------
__global__ void apply_kernel(float* __restrict__ out) {
    const int i = blockIdx.x * blockDim.x + threadIdx.x;   // float4 index
    float4 v = ((float4*)out)[i];
    const int c = (i * 4) & (C2C - 1);
    v.x = fmaxf(fmaf(v.x, g_scale2[c + 0], g_shift2[c + 0]), 0.f);
    v.y = fmaxf(fmaf(v.y, g_scale2[c + 1], g_shift2[c + 1]), 0.f);
    v.z = fmaxf(fmaf(v.z, g_scale2[c + 2], g_shift2[c + 2]), 0.f);
    v.w = fmaxf(fmaf(v.w, g_scale2[c + 3], g_shift2[c + 3]), 0.f);
    ((float4*)out)[i] = v;
}

// ---------------- launch -----------------------------------------------------
extern "C" void kernel_launch(void* const* d_in, const int* in_sizes, int n_in,
                              void* d_out, int out_size) {
    const float* xyz1    = (const float*)d_in[0];
    const float* xyz2    = (const float*)d_in[1];
    const float* points1 = (const float*)d_in[2];
    const float* points2 = (const float*)d_in[3];
    const float* W1      = (const float*)d_in[4];
    const float* g1      = (const float*)d_in[5];
    const float* b1      = (const float*)d_in[6];
    const float* W2      = (const float*)d_in[7];
    const float* g2      = (const float*)d_in[8];
    const float* b2      = (const float*)d_in[9];
    float* out = (float*)d_out;
    (void)in_sizes; (void)n_in; (void)out_size;

    cudaFuncSetAttribute(gemm_mma_kernel<0>, cudaFuncAttributeMaxDynamicSharedMemorySize, SMEM_GEMM);
    cudaFuncSetAttribute(gemm_mma_kernel<1>, cudaFuncAttributeMaxDynamicSharedMemorySize, SMEM_GEMM);
    cudaFuncSetAttribute(gemm_mma_kernel<2>, cudaFuncAttributeMaxDynamicSharedMemorySize, SMEM_GEMM);

    prep_kernel<<<4153, 256>>>(points2, points1, W1, W2);                    // 0
    knn_kernel<<<dim3(NPTS / 256, BDIM), 256>>>(xyz1, xyz2);                 // 1
    gemm_mma_kernel<0><<<dim3(BDIM*SPTS/128, C1C/128), 256, SMEM_GEMM>>>(nullptr); // 2
    gemm_mma_kernel<1><<<dim3(BNROWS/128,    C1C/128), 256, SMEM_GEMM>>>(nullptr); // 3 (+stats1)
    finalize_kernel<<<1, 256>>>(g1, b1, 0);                                  // 4
    conv_a1_kernel<<<(BNROWS*C1C)/2048, 256>>>();                            // 5
    gemm_mma_kernel<2><<<dim3(BNROWS/128, C2C/128), 256, SMEM_GEMM>>>(out);  // 6 (+stats2)
    finalize_kernel<<<1, 256>>>(g2, b2, 1);                                  // 7
    apply_kernel<<<(BNROWS * C2C / 4) / 256, 256>>>(out);                    // 8
}